// round 2
// baseline (speedup 1.0000x reference)
#include <cuda_runtime.h>
#include <cstdint>

// ---------------------------------------------------------------------------
// SelfAttention: out = softmax((xWq^T+bq)(xWk^T+bk)^T / sqrt(D)) (xWv^T+bv)
// B=4, S=2048, D=1024. fp32 I/O, TF32 tensor-core GEMMs, fp32 accumulate.
// Round 1: software-pipelined global loads (prefetch into registers during MMA).
// ---------------------------------------------------------------------------

#define DEV_INLINE __device__ __forceinline__

static constexpr int Bsz = 4;
static constexpr int S   = 2048;
static constexpr int D   = 1024;
static constexpr int MQK = Bsz * S;          // 8192 rows for QKV projection

// Scratch (static __device__ arrays: allocation-free per harness rules)
__device__ float g_q[(size_t)MQK * D];
__device__ float g_k[(size_t)MQK * D];
__device__ float g_v[(size_t)MQK * D];
__device__ float g_s[(size_t)Bsz * S * S];

DEV_INLINE float tf32_round(float x) {
    uint32_t u;
    asm("cvt.rna.tf32.f32 %0, %1;" : "=r"(u) : "f"(x));
    return __uint_as_float(u);
}

DEV_INLINE void mma_16x8x8(float acc[4], const uint32_t a[4], const uint32_t b[2]) {
    asm volatile(
        "mma.sync.aligned.m16n8k8.row.col.f32.tf32.tf32.f32 "
        "{%0,%1,%2,%3}, {%4,%5,%6,%7}, {%8,%9}, {%0,%1,%2,%3};\n"
        : "+f"(acc[0]), "+f"(acc[1]), "+f"(acc[2]), "+f"(acc[3])
        : "r"(a[0]), "r"(a[1]), "r"(a[2]), "r"(a[3]),
          "r"(b[0]), "r"(b[1]));
}

// ---------------------------------------------------------------------------
// Unified TF32 GEMM:
//   C[m,n] = alpha * sum_k A[m,k] * Bop[k,n]  (+ bias[n] if bias != nullptr)
// TRANSB == false: B is [N,K] row-major (k-major rows)  -> C = A @ B^T  ("NT")
// TRANSB == true : B is [K,N] row-major                 -> C = A @ B    ("NN")
// blockIdx.z batches via the given strides.
// Block tile 128x64, K-chunk 32, 256 threads (8 warps, 4x2 warp grid, 32x32/warp).
// Global loads for tile k+1 are issued BEFORE the compute on tile k, so the
// LDG latency is hidden behind 32 MMAs.
// ---------------------------------------------------------------------------
template <bool TRANSB>
__global__ void __launch_bounds__(256)
gemm_tf32_kernel(const float* __restrict__ A, int lda, long long strideA,
                 const float* __restrict__ B, int ldb, long long strideB,
                 float* __restrict__ C, int ldc, long long strideC,
                 const float* __restrict__ bias,
                 int M, int N, int K, float alpha)
{
    constexpr int BM = 128, BN = 64, BK = 32;
    constexpr int LDS_STRIDE = BK + 4;   // 36 floats: 16B-aligned rows, conflict-free

    __shared__ float As[BM][LDS_STRIDE];
    __shared__ float Bs[BN][LDS_STRIDE];

    const int bz = blockIdx.z;
    A += (size_t)bz * strideA;
    B += (size_t)bz * strideB;
    C += (size_t)bz * strideC;

    const int bm = blockIdx.y * BM;
    const int bn = blockIdx.x * BN;

    const int tid   = threadIdx.x;
    const int warp  = tid >> 5;
    const int lane  = tid & 31;
    const int wm    = warp & 3;          // 4 warps along M
    const int wn    = warp >> 2;         // 2 warps along N
    const int m_w   = wm * 32;
    const int n_w   = wn * 32;
    const int group = lane >> 2;         // 0..7
    const int tig   = lane & 3;          // 0..3

    // Per-thread load coordinates
    const int aq  = tid & 7;             // 8 float4 per 32-float A row
    const int ar0 = tid >> 3;            // 0..31
    const int bq  = TRANSB ? (tid & 15) : (tid & 7);
    const int br0 = TRANSB ? (tid >> 4) : (tid >> 3);

    float acc[2][4][4];
    #pragma unroll
    for (int i = 0; i < 2; i++)
        #pragma unroll
        for (int j = 0; j < 4; j++)
            #pragma unroll
            for (int r = 0; r < 4; r++) acc[i][j][r] = 0.0f;

    float4 aP[4];   // prefetched A tile fragment
    float4 bP[2];   // prefetched B tile fragment

    // ---- prologue: load tile k0 = 0 ----
    #pragma unroll
    for (int i = 0; i < 4; i++)
        aP[i] = *reinterpret_cast<const float4*>(
            &A[(size_t)(bm + ar0 + 32 * i) * lda + aq * 4]);
    if (!TRANSB) {
        #pragma unroll
        for (int i = 0; i < 2; i++)
            bP[i] = *reinterpret_cast<const float4*>(
                &B[(size_t)(bn + br0 + 32 * i) * ldb + bq * 4]);
    } else {
        #pragma unroll
        for (int i = 0; i < 2; i++)
            bP[i] = *reinterpret_cast<const float4*>(
                &B[(size_t)(br0 + 16 * i) * ldb + bn + bq * 4]);
    }

    for (int k0 = 0; k0 < K; k0 += BK) {
        // ---- commit prefetched tile to smem (with tf32 rounding) ----
        #pragma unroll
        for (int i = 0; i < 4; i++) {
            float4 w = make_float4(tf32_round(aP[i].x), tf32_round(aP[i].y),
                                   tf32_round(aP[i].z), tf32_round(aP[i].w));
            *reinterpret_cast<float4*>(&As[ar0 + 32 * i][aq * 4]) = w;
        }
        if (!TRANSB) {
            #pragma unroll
            for (int i = 0; i < 2; i++) {
                float4 w = make_float4(tf32_round(bP[i].x), tf32_round(bP[i].y),
                                       tf32_round(bP[i].z), tf32_round(bP[i].w));
                *reinterpret_cast<float4*>(&Bs[br0 + 32 * i][bq * 4]) = w;
            }
        } else {
            #pragma unroll
            for (int i = 0; i < 2; i++) {
                const int kr = br0 + 16 * i;
                Bs[bq * 4 + 0][kr] = tf32_round(bP[i].x);
                Bs[bq * 4 + 1][kr] = tf32_round(bP[i].y);
                Bs[bq * 4 + 2][kr] = tf32_round(bP[i].z);
                Bs[bq * 4 + 3][kr] = tf32_round(bP[i].w);
            }
        }
        __syncthreads();

        // ---- issue next tile's global loads (latency hidden by MMAs below) ----
        const int kn = k0 + BK;
        if (kn < K) {
            #pragma unroll
            for (int i = 0; i < 4; i++)
                aP[i] = *reinterpret_cast<const float4*>(
                    &A[(size_t)(bm + ar0 + 32 * i) * lda + kn + aq * 4]);
            if (!TRANSB) {
                #pragma unroll
                for (int i = 0; i < 2; i++)
                    bP[i] = *reinterpret_cast<const float4*>(
                        &B[(size_t)(bn + br0 + 32 * i) * ldb + kn + bq * 4]);
            } else {
                #pragma unroll
                for (int i = 0; i < 2; i++)
                    bP[i] = *reinterpret_cast<const float4*>(
                        &B[(size_t)(kn + br0 + 16 * i) * ldb + bn + bq * 4]);
            }
        }

        // ---- compute: 4 k-steps of 8 ----
        #pragma unroll
        for (int ks = 0; ks < BK; ks += 8) {
            uint32_t afr[2][4];
            #pragma unroll
            for (int mi = 0; mi < 2; mi++) {
                const int r = m_w + mi * 16;
                afr[mi][0] = __float_as_uint(As[r + group    ][ks + tig    ]);
                afr[mi][1] = __float_as_uint(As[r + group + 8][ks + tig    ]);
                afr[mi][2] = __float_as_uint(As[r + group    ][ks + tig + 4]);
                afr[mi][3] = __float_as_uint(As[r + group + 8][ks + tig + 4]);
            }
            uint32_t bfr[4][2];
            #pragma unroll
            for (int ni = 0; ni < 4; ni++) {
                const int c = n_w + ni * 8;
                bfr[ni][0] = __float_as_uint(Bs[c + group][ks + tig    ]);
                bfr[ni][1] = __float_as_uint(Bs[c + group][ks + tig + 4]);
            }
            #pragma unroll
            for (int mi = 0; mi < 2; mi++)
                #pragma unroll
                for (int ni = 0; ni < 4; ni++)
                    mma_16x8x8(acc[mi][ni], afr[mi], bfr[ni]);
        }
        __syncthreads();
    }

    // ---- epilogue ----
    #pragma unroll
    for (int mi = 0; mi < 2; mi++) {
        const int row0 = bm + m_w + mi * 16 + group;
        #pragma unroll
        for (int ni = 0; ni < 4; ni++) {
            const int col0 = bn + n_w + ni * 8 + tig * 2;
            float b0 = 0.f, b1 = 0.f;
            if (bias) { b0 = bias[col0]; b1 = bias[col0 + 1]; }
            C[(size_t)row0 * ldc + col0    ]       = acc[mi][ni][0] * alpha + b0;
            C[(size_t)row0 * ldc + col0 + 1]       = acc[mi][ni][1] * alpha + b1;
            C[(size_t)(row0 + 8) * ldc + col0    ] = acc[mi][ni][2] * alpha + b0;
            C[(size_t)(row0 + 8) * ldc + col0 + 1] = acc[mi][ni][3] * alpha + b1;
        }
    }
}

// ---------------------------------------------------------------------------
// Row softmax, in place. One block (256 threads) per row of 2048 floats.
// ---------------------------------------------------------------------------
__global__ void __launch_bounds__(256)
softmax_kernel(float* __restrict__ Smat, int ncols)
{
    float* p = Smat + (size_t)blockIdx.x * ncols;
    const int tid  = threadIdx.x;
    const int warp = tid >> 5;
    const int lane = tid & 31;

    __shared__ float red_max[8];
    __shared__ float red_sum[8];

    float v[8];
    float mx = -1e30f;
    #pragma unroll
    for (int i = 0; i < 8; i++) {
        v[i] = p[tid + 256 * i];
        mx = fmaxf(mx, v[i]);
    }
    #pragma unroll
    for (int o = 16; o > 0; o >>= 1)
        mx = fmaxf(mx, __shfl_xor_sync(0xffffffffu, mx, o));
    if (lane == 0) red_max[warp] = mx;
    __syncthreads();
    float m = red_max[0];
    #pragma unroll
    for (int w = 1; w < 8; w++) m = fmaxf(m, red_max[w]);

    float sum = 0.f;
    #pragma unroll
    for (int i = 0; i < 8; i++) {
        v[i] = __expf(v[i] - m);
        sum += v[i];
    }
    #pragma unroll
    for (int o = 16; o > 0; o >>= 1)
        sum += __shfl_xor_sync(0xffffffffu, sum, o);
    if (lane == 0) red_sum[warp] = sum;
    __syncthreads();
    float total = 0.f;
    #pragma unroll
    for (int w = 0; w < 8; w++) total += red_sum[w];

    const float inv = 1.0f / total;
    #pragma unroll
    for (int i = 0; i < 8; i++)
        p[tid + 256 * i] = v[i] * inv;
}

// ---------------------------------------------------------------------------
extern "C" void kernel_launch(void* const* d_in, const int* in_sizes, int n_in,
                              void* d_out, int out_size)
{
    const float* x  = (const float*)d_in[0];
    const float* Wq = (const float*)d_in[1];
    const float* bq = (const float*)d_in[2];
    const float* Wk = (const float*)d_in[3];
    const float* bk = (const float*)d_in[4];
    const float* Wv = (const float*)d_in[5];
    const float* bv = (const float*)d_in[6];
    float* out = (float*)d_out;

    float *gq, *gk, *gv, *gs;
    cudaGetSymbolAddress((void**)&gq, g_q);
    cudaGetSymbolAddress((void**)&gk, g_k);
    cudaGetSymbolAddress((void**)&gv, g_v);
    cudaGetSymbolAddress((void**)&gs, g_s);

    const dim3 blk(256);

    // 1) QKV projections: [8192,1024] = x[8192,1024] @ W^T[1024,1024] + b
    {
        const dim3 grid(D / 64, MQK / 128, 1);
        gemm_tf32_kernel<false><<<grid, blk>>>(x, D, 0, Wq, D, 0, gq, D, 0, bq,
                                               MQK, D, D, 1.0f);
        gemm_tf32_kernel<false><<<grid, blk>>>(x, D, 0, Wk, D, 0, gk, D, 0, bk,
                                               MQK, D, D, 1.0f);
        gemm_tf32_kernel<false><<<grid, blk>>>(x, D, 0, Wv, D, 0, gv, D, 0, bv,
                                               MQK, D, D, 1.0f);
    }

    // 2) scores[b] = Q[b] @ K[b]^T * (1/sqrt(D))
    {
        const dim3 grid(S / 64, S / 128, Bsz);
        gemm_tf32_kernel<false><<<grid, blk>>>(
            gq, D, (long long)S * D,
            gk, D, (long long)S * D,
            gs, S, (long long)S * S,
            nullptr, S, S, D, 0.03125f /* 1/sqrt(1024) */);
    }

    // 3) row softmax over all B*S rows
    softmax_kernel<<<Bsz * S, blk>>>(gs, S);

    // 4) out[b] = P[b] @ V[b]   (B is [K,N] row-major -> TRANSB path)
    {
        const dim3 grid(D / 64, S / 128, Bsz);
        gemm_tf32_kernel<true><<<grid, blk>>>(
            gs, S, (long long)S * S,
            gv, D, (long long)S * D,
            out, D, (long long)S * D,
            nullptr, S, D, S, 1.0f);
    }
}

// round 4
// speedup vs baseline: 1.5081x; 1.5081x over previous
#include <cuda_runtime.h>
#include <cstdint>

// ---------------------------------------------------------------------------
// SelfAttention: out = softmax((xWq^T+bq)(xWk^T+bk)^T / sqrt(D)) (xWv^T+bv)
// B=4, S=2048, D=1024. fp32 I/O.
// Round 3: sm_100-compatible mma.sync TF32 path (tcgen05 unavailable at this
// compile target). 64x64 warp tiles (16 FLOP/LDS-byte), cp.async double
// buffering, operands pre-rounded to tf32 in gmem so raw-copy loads are exact.
// ---------------------------------------------------------------------------

#define DEV_INLINE __device__ __forceinline__

static constexpr int Bsz = 4;
static constexpr int S   = 2048;
static constexpr int D   = 1024;
static constexpr int MQK = Bsz * S;

// Scratch (static __device__ arrays: allocation-free per harness rules)
__device__ float g_q [(size_t)MQK * D];
__device__ float g_k [(size_t)MQK * D];
__device__ float g_vT[(size_t)Bsz * D * S];   // V stored transposed per batch
__device__ float g_s [(size_t)Bsz * S * S];   // scores; prologue also aliases
                                              // rounded x / W copies here

DEV_INLINE float tf32_round(float x) {
    uint32_t u;
    asm("cvt.rna.tf32.f32 %0, %1;" : "=r"(u) : "f"(x));
    return __uint_as_float(u);
}

DEV_INLINE uint32_t smem_u32(const void* p) {
    uint32_t a;
    asm("{ .reg .u64 t; cvta.to.shared.u64 t, %1; cvt.u32.u64 %0, t; }"
        : "=r"(a) : "l"(p));
    return a;
}

DEV_INLINE void cp_async16(uint32_t dst, const void* src) {
    asm volatile("cp.async.cg.shared.global [%0], [%1], 16;"
                 :: "r"(dst), "l"(src) : "memory");
}
DEV_INLINE void cp_commit() {
    asm volatile("cp.async.commit_group;" ::: "memory");
}
template <int N> DEV_INLINE void cp_wait() {
    asm volatile("cp.async.wait_group %0;" :: "n"(N) : "memory");
}

DEV_INLINE void mma_16x8x8(float acc[4], const uint32_t a[4], const uint32_t b[2]) {
    asm volatile(
        "mma.sync.aligned.m16n8k8.row.col.f32.tf32.tf32.f32 "
        "{%0,%1,%2,%3}, {%4,%5,%6,%7}, {%8,%9}, {%0,%1,%2,%3};\n"
        : "+f"(acc[0]), "+f"(acc[1]), "+f"(acc[2]), "+f"(acc[3])
        : "r"(a[0]), "r"(a[1]), "r"(a[2]), "r"(a[3]),
          "r"(b[0]), "r"(b[1]));
}

// ---------------------------------------------------------------------------
// Elementwise tf32 rounding copy (prep pass for x and the weights)
// ---------------------------------------------------------------------------
__global__ void __launch_bounds__(256)
round_copy_kernel(const float* __restrict__ src, float* __restrict__ dst, int n4)
{
    const int i = blockIdx.x * 256 + threadIdx.x;
    if (i < n4) {
        float4 v = reinterpret_cast<const float4*>(src)[i];
        v.x = tf32_round(v.x); v.y = tf32_round(v.y);
        v.z = tf32_round(v.z); v.w = tf32_round(v.w);
        reinterpret_cast<float4*>(dst)[i] = v;
    }
}

// ---------------------------------------------------------------------------
// TF32 NT GEMM: C[m,n] = alpha * sum_k A[m,k]*B[n,k]  (+bias[n])
// A: [M,K] row-major, B: [N,K] row-major, both ALREADY tf32-valued in gmem.
// CTA 128x128x(BK=32), 128 threads = 4 warps of 64x64.
// cp.async double-buffered. blockIdx.z batches.
// STORE_T: store C transposed (C[n][m], ldc = leading dim of that layout).
// ROUND_OUT: round result to tf32 before store (so it can feed a later GEMM).
// ---------------------------------------------------------------------------
static constexpr int BM = 128, BN = 128, BK = 32;
static constexpr int ROWF  = BK + 4;             // 36 floats/row (16B-aligned)
static constexpr int STG   = BM * ROWF;          // floats per operand stage
static constexpr int DYN_SMEM = 4 * STG * 4;     // 2 stages x (A+B) = 73728 B

template <bool STORE_T, bool ROUND_OUT>
__global__ void __launch_bounds__(128)
gemm_mma_kernel(const float* __restrict__ A, int lda, long long strideA,
                const float* __restrict__ B, int ldb, long long strideB,
                float* __restrict__ C, int ldc, long long strideC,
                const float* __restrict__ bias, int K, float alpha)
{
    extern __shared__ float dyn[];
    float* As = dyn;                 // [2][STG]
    float* Bs = dyn + 2 * STG;       // [2][STG]
    const uint32_t sA = smem_u32(As);
    const uint32_t sB = smem_u32(Bs);

    const int tid  = threadIdx.x;
    const int wid  = tid >> 5;
    const int lane = tid & 31;
    const int wm   = wid & 1;                // 2 warps along M
    const int wn   = wid >> 1;               // 2 warps along N
    const int m_w  = wm * 64;
    const int n_w  = wn * 64;
    const int group = lane >> 2;             // 0..7
    const int tig   = lane & 3;              // 0..3

    const int bz = blockIdx.z;
    A += (size_t)bz * strideA;
    B += (size_t)bz * strideB;
    C += (size_t)bz * strideC;
    const int bm = blockIdx.y * BM;
    const int bn = blockIdx.x * BN;

    float acc[4][8][4];
    #pragma unroll
    for (int mi = 0; mi < 4; mi++)
        #pragma unroll
        for (int ni = 0; ni < 8; ni++)
            #pragma unroll
            for (int r = 0; r < 4; r++) acc[mi][ni][r] = 0.0f;

    // loader: 8 float4 per operand per thread (128 rows x 8 float4-cols)
    auto load_stage = [&](int s, int k0) {
        const uint32_t offA = sA + (uint32_t)s * STG * 4;
        const uint32_t offB = sB + (uint32_t)s * STG * 4;
        #pragma unroll
        for (int i = 0; i < 8; i++) {
            const int idx = tid + 128 * i;
            const int r = idx >> 3, c4 = idx & 7;
            cp_async16(offA + (uint32_t)(r * ROWF + c4 * 4) * 4,
                       &A[(size_t)(bm + r) * lda + k0 + c4 * 4]);
        }
        #pragma unroll
        for (int i = 0; i < 8; i++) {
            const int idx = tid + 128 * i;
            const int r = idx >> 3, c4 = idx & 7;
            cp_async16(offB + (uint32_t)(r * ROWF + c4 * 4) * 4,
                       &B[(size_t)(bn + r) * ldb + k0 + c4 * 4]);
        }
        cp_commit();
    };

    const int nst = K / BK;
    load_stage(0, 0);

    for (int i = 0; i < nst; i++) {
        if (i + 1 < nst) {
            load_stage((i + 1) & 1, (i + 1) * BK);
            cp_wait<1>();
        } else {
            cp_wait<0>();
        }
        __syncthreads();

        const float* as = As + (i & 1) * STG;
        const float* bs = Bs + (i & 1) * STG;

        #pragma unroll
        for (int ks = 0; ks < BK; ks += 8) {
            uint32_t afr[4][4];
            #pragma unroll
            for (int mi = 0; mi < 4; mi++) {
                const int r = m_w + mi * 16;
                afr[mi][0] = __float_as_uint(as[(r + group    ) * ROWF + ks + tig    ]);
                afr[mi][1] = __float_as_uint(as[(r + group + 8) * ROWF + ks + tig    ]);
                afr[mi][2] = __float_as_uint(as[(r + group    ) * ROWF + ks + tig + 4]);
                afr[mi][3] = __float_as_uint(as[(r + group + 8) * ROWF + ks + tig + 4]);
            }
            uint32_t bfr[8][2];
            #pragma unroll
            for (int ni = 0; ni < 8; ni++) {
                const int c = n_w + ni * 8;
                bfr[ni][0] = __float_as_uint(bs[(c + group) * ROWF + ks + tig    ]);
                bfr[ni][1] = __float_as_uint(bs[(c + group) * ROWF + ks + tig + 4]);
            }
            #pragma unroll
            for (int mi = 0; mi < 4; mi++)
                #pragma unroll
                for (int ni = 0; ni < 8; ni++)
                    mma_16x8x8(acc[mi][ni], afr[mi], bfr[ni]);
        }
        __syncthreads();
    }

    // ---- epilogue ----
    #pragma unroll
    for (int mi = 0; mi < 4; mi++) {
        const int row0 = bm + m_w + mi * 16 + group;
        #pragma unroll
        for (int ni = 0; ni < 8; ni++) {
            const int col0 = bn + n_w + ni * 8 + tig * 2;
            float v00 = acc[mi][ni][0] * alpha;
            float v01 = acc[mi][ni][1] * alpha;
            float v10 = acc[mi][ni][2] * alpha;
            float v11 = acc[mi][ni][3] * alpha;
            if (bias) {
                const float b0 = bias[col0], b1 = bias[col0 + 1];
                v00 += b0; v01 += b1; v10 += b0; v11 += b1;
            }
            if (ROUND_OUT) {
                v00 = tf32_round(v00); v01 = tf32_round(v01);
                v10 = tf32_round(v10); v11 = tf32_round(v11);
            }
            if (!STORE_T) {
                *reinterpret_cast<float2*>(&C[(size_t)row0 * ldc + col0]) =
                    make_float2(v00, v01);
                *reinterpret_cast<float2*>(&C[(size_t)(row0 + 8) * ldc + col0]) =
                    make_float2(v10, v11);
            } else {
                C[(size_t)col0 * ldc + row0]           = v00;
                C[(size_t)(col0 + 1) * ldc + row0]     = v01;
                C[(size_t)col0 * ldc + row0 + 8]       = v10;
                C[(size_t)(col0 + 1) * ldc + row0 + 8] = v11;
            }
        }
    }
}

// ---------------------------------------------------------------------------
// Row softmax, in place, output rounded to tf32 (feeds the PV GEMM).
// One block (256 threads) per row of 2048 floats.
// ---------------------------------------------------------------------------
__global__ void __launch_bounds__(256)
softmax_kernel(float* __restrict__ Smat, int ncols)
{
    float* p = Smat + (size_t)blockIdx.x * ncols;
    const int tid  = threadIdx.x;
    const int warp = tid >> 5;
    const int lane = tid & 31;

    __shared__ float red_max[8];
    __shared__ float red_sum[8];

    float v[8];
    float mx = -1e30f;
    #pragma unroll
    for (int i = 0; i < 8; i++) {
        v[i] = p[tid + 256 * i];
        mx = fmaxf(mx, v[i]);
    }
    #pragma unroll
    for (int o = 16; o > 0; o >>= 1)
        mx = fmaxf(mx, __shfl_xor_sync(0xffffffffu, mx, o));
    if (lane == 0) red_max[warp] = mx;
    __syncthreads();
    float m = red_max[0];
    #pragma unroll
    for (int w = 1; w < 8; w++) m = fmaxf(m, red_max[w]);

    float sum = 0.f;
    #pragma unroll
    for (int i = 0; i < 8; i++) {
        v[i] = __expf(v[i] - m);
        sum += v[i];
    }
    #pragma unroll
    for (int o = 16; o > 0; o >>= 1)
        sum += __shfl_xor_sync(0xffffffffu, sum, o);
    if (lane == 0) red_sum[warp] = sum;
    __syncthreads();
    float total = 0.f;
    #pragma unroll
    for (int w = 0; w < 8; w++) total += red_sum[w];

    const float inv = 1.0f / total;
    #pragma unroll
    for (int i = 0; i < 8; i++)
        p[tid + 256 * i] = tf32_round(v[i] * inv);
}

// ---------------------------------------------------------------------------
extern "C" void kernel_launch(void* const* d_in, const int* in_sizes, int n_in,
                              void* d_out, int out_size)
{
    const float* x  = (const float*)d_in[0];
    const float* Wq = (const float*)d_in[1];
    const float* bq = (const float*)d_in[2];
    const float* Wk = (const float*)d_in[3];
    const float* bk = (const float*)d_in[4];
    const float* Wv = (const float*)d_in[5];
    const float* bv = (const float*)d_in[6];
    float* out = (float*)d_out;

    float *gq, *gk, *gvT, *gs;
    cudaGetSymbolAddress((void**)&gq,  g_q);
    cudaGetSymbolAddress((void**)&gk,  g_k);
    cudaGetSymbolAddress((void**)&gvT, g_vT);
    cudaGetSymbolAddress((void**)&gs,  g_s);

    // tf32-rounded copies of x and weights, aliased into g_s (not yet live;
    // g_s is first written by the scores GEMM, which runs after QKV).
    float* xr  = gs;                                   // 8192*1024
    float* wqr = gs + (size_t)MQK * D;                 // 1024*1024
    float* wkr = wqr + (size_t)D * D;
    float* wvr = wkr + (size_t)D * D;

    cudaFuncSetAttribute(gemm_mma_kernel<false, true>,
                         cudaFuncAttributeMaxDynamicSharedMemorySize, DYN_SMEM);
    cudaFuncSetAttribute(gemm_mma_kernel<true, true>,
                         cudaFuncAttributeMaxDynamicSharedMemorySize, DYN_SMEM);
    cudaFuncSetAttribute(gemm_mma_kernel<false, false>,
                         cudaFuncAttributeMaxDynamicSharedMemorySize, DYN_SMEM);

    // 0) prep: round x, Wq, Wk, Wv to tf32 values in gmem
    {
        const int nx4 = MQK * D / 4, nw4 = D * D / 4;
        round_copy_kernel<<<(nx4 + 255) / 256, 256>>>(x,  xr,  nx4);
        round_copy_kernel<<<(nw4 + 255) / 256, 256>>>(Wq, wqr, nw4);
        round_copy_kernel<<<(nw4 + 255) / 256, 256>>>(Wk, wkr, nw4);
        round_copy_kernel<<<(nw4 + 255) / 256, 256>>>(Wv, wvr, nw4);
    }

    const dim3 blk(128);

    // 1) QKV projections: [8192,1024] = x @ W^T + b (NT). Outputs rounded.
    //    V written transposed into g_vT[b][d][s].
    {
        const dim3 grid(D / BN, MQK / BM, 1);
        gemm_mma_kernel<false, true><<<grid, blk, DYN_SMEM>>>(
            xr, D, 0, wqr, D, 0, gq, D, 0, bq, D, 1.0f);
        gemm_mma_kernel<false, true><<<grid, blk, DYN_SMEM>>>(
            xr, D, 0, wkr, D, 0, gk, D, 0, bk, D, 1.0f);
    }
    {
        // V: batch via blockIdx.z so the transposed store lands in g_vT[b]
        const dim3 grid(D / BN, S / BM, Bsz);
        gemm_mma_kernel<true, true><<<grid, blk, DYN_SMEM>>>(
            xr,  D, (long long)S * D,
            wvr, D, 0,
            gvT, S, (long long)D * S,
            bv, D, 1.0f);
    }

    // 2) scores[b] = Q[b] @ K[b]^T * (1/sqrt(D))  (overwrites the aliased prep data)
    {
        const dim3 grid(S / BN, S / BM, Bsz);
        gemm_mma_kernel<false, false><<<grid, blk, DYN_SMEM>>>(
            gq, D, (long long)S * D,
            gk, D, (long long)S * D,
            gs, S, (long long)S * S,
            nullptr, D, 0.03125f /* 1/sqrt(1024) */);
    }

    // 3) row softmax (tf32-rounded output)
    softmax_kernel<<<Bsz * S, 256>>>(gs, S);

    // 4) out[b] = P[b] @ V[b] = P[b] @ (vT[b])^T  (NT path)
    {
        const dim3 grid(D / BN, S / BM, Bsz);
        gemm_mma_kernel<false, false><<<grid, blk, DYN_SMEM>>>(
            gs,  S, (long long)S * S,
            gvT, S, (long long)D * S,
            out, D, (long long)S * D,
            nullptr, S, 1.0f);
    }
}